// round 10
// baseline (speedup 1.0000x reference)
#include <cuda_runtime.h>
#include <cuda_fp16.h>
#include <cuda_fp8.h>
#include <stdint.h>
#include <math.h>

// Problem constants (fixed by dataset)
#define Bsz  8
#define Qlen 2048
#define Klen 2048
#define Hdim 128
#define BM   64          // queries per CTA
#define BN   64          // keys per tile
#define NT   128         // 4 warps
#define NTILE (Klen / BN)

#define KTOT (Bsz * Klen * Hdim)   // 2,097,152 elements

// Pre-split history scratch, row-major [b][key][h]:
//   g_khi : fp16 hi = fl16(k)
//   g_klo8: e4m3( (k - hi) * 2^12 )
//   g_khi8: e4m3( hi )
__device__ __align__(16) __half  g_khi[KTOT];
__device__ __align__(16) uint8_t g_klo8[KTOT];
__device__ __align__(16) uint8_t g_khi8[KTOT];

// stage: [hi16 swizzled 16KB][lo8 8KB][hi8 8KB]; double buffered = 64KB
#define OFF_LO8    16384
#define OFF_HI8    24576
#define TILE_BYTES 32768
#define SMEM_BYTES (2 * TILE_BYTES)

#define LOG2E  1.4426950408889634f
#define SCL    4096.0f
#define INVSCL 2.44140625e-4f      // 2^-12
#define ONESF16X2 0x3C003C00u      // half2(1.0, 1.0)

__device__ __forceinline__ uint32_t smem_u32(const void* p) {
    uint32_t a;
    asm("{ .reg .u64 t; cvta.to.shared.u64 t, %1; cvt.u32.u64 %0, t; }" : "=r"(a) : "l"(p));
    return a;
}
__device__ __forceinline__ uint32_t h2u(__half2 h) { return *reinterpret_cast<uint32_t*>(&h); }
__device__ __forceinline__ float ex2f(float x) {
    float y; asm("ex2.approx.ftz.f32 %0, %1;" : "=f"(y) : "f"(x)); return y;
}
__device__ __forceinline__ uint32_t ex2h2(uint32_t x) {
    uint32_t y; asm("ex2.approx.f16x2 %0, %1;" : "=r"(y) : "r"(x)); return y;
}

// fp32 pair -> fp16 hi + fp16 residual(lo), packed half2
__device__ __forceinline__ void split_h2(float x, float y, uint32_t& hi, uint32_t& lo) {
    __half2 h = __floats2half2_rn(x, y);
    float rx = x - __half2float(__low2half(h));
    float ry = y - __half2float(__high2half(h));
    __half2 l = __floats2half2_rn(rx, ry);
    hi = h2u(h); lo = h2u(l);
}
__device__ __forceinline__ uint32_t pk8(float a, float b, float c, float d) {
    float4 v = make_float4(a, b, c, d);
    __nv_fp8x4_e4m3 p(v);
    return *reinterpret_cast<uint32_t*>(&p);
}

// XOR-swizzled fp16 tile offset: row in [0,64), bytecol in [0,256)
__device__ __forceinline__ uint32_t swz2(int row, int bytecol) {
    int ch = bytecol >> 4;
    int chs = (ch & 8) | ((ch ^ row) & 7);
    return (uint32_t)(row * 256 + (chs << 4));
}
// XOR-swizzled fp8 tile offset: row in [0,64), bytecol in [0,128)
__device__ __forceinline__ uint32_t swz8(int row, int bytecol) {
    int chs = ((bytecol >> 4) ^ row) & 7;
    return (uint32_t)(row * 128 + (chs << 4));
}

__device__ __forceinline__ void cpa16(uint32_t dst, const void* src) {
    asm volatile("cp.async.cg.shared.global [%0], [%1], 16;" :: "r"(dst), "l"(src));
}
#define CP_COMMIT() asm volatile("cp.async.commit_group;" ::: "memory")
#define CP_WAIT0()  asm volatile("cp.async.wait_group 0;" ::: "memory")

__device__ __forceinline__ void ldsm_x4(uint32_t& r0, uint32_t& r1, uint32_t& r2, uint32_t& r3,
                                        uint32_t addr) {
    asm volatile("ldmatrix.sync.aligned.m8n8.x4.shared.b16 {%0,%1,%2,%3}, [%4];"
                 : "=r"(r0), "=r"(r1), "=r"(r2), "=r"(r3) : "r"(addr));
}
__device__ __forceinline__ void ldsm_x4_t(uint32_t& r0, uint32_t& r1, uint32_t& r2, uint32_t& r3,
                                          uint32_t addr) {
    asm volatile("ldmatrix.sync.aligned.m8n8.x4.trans.shared.b16 {%0,%1,%2,%3}, [%4];"
                 : "=r"(r0), "=r"(r1), "=r"(r2), "=r"(r3) : "r"(addr));
}
// D(16x8,f32) += A(16x16,f16) * B(16x8,f16)
__device__ __forceinline__ void mma16816(float* d, const uint32_t* a, uint32_t b0, uint32_t b1) {
    asm volatile("mma.sync.aligned.m16n8k16.row.col.f32.f16.f16.f32 "
                 "{%0,%1,%2,%3}, {%4,%5,%6,%7}, {%8,%9}, {%0,%1,%2,%3};"
                 : "+f"(d[0]), "+f"(d[1]), "+f"(d[2]), "+f"(d[3])
                 : "r"(a[0]), "r"(a[1]), "r"(a[2]), "r"(a[3]), "r"(b0), "r"(b1));
}
// D(16x8,f32) += A(16x32,e4m3) * B(32x8,e4m3)
__device__ __forceinline__ void mma_fp8(float* d, const uint32_t* a, uint32_t b0, uint32_t b1) {
    asm volatile("mma.sync.aligned.m16n8k32.row.col.f32.e4m3.e4m3.f32 "
                 "{%0,%1,%2,%3}, {%4,%5,%6,%7}, {%8,%9}, {%0,%1,%2,%3};"
                 : "+f"(d[0]), "+f"(d[1]), "+f"(d[2]), "+f"(d[3])
                 : "r"(a[0]), "r"(a[1]), "r"(a[2]), "r"(a[3]), "r"(b0), "r"(b1));
}

// ---------------- Pre-pass: split history fp32 -> fp16 hi + fp8 cross operands ----------------
__global__ __launch_bounds__(256)
void prep_split(const float* __restrict__ history)
{
    const size_t i = ((size_t)blockIdx.x * 256 + threadIdx.x) * 8;
    float4 a = *(const float4*)(history + i);
    float4 b = *(const float4*)(history + i + 4);

    float x[8] = {a.x, a.y, a.z, a.w, b.x, b.y, b.z, b.w};
    float hf[8], lf[8];
    uint32_t hh[4];
    #pragma unroll
    for (int j = 0; j < 4; ++j) {
        __half2 h = __floats2half2_rn(x[2*j], x[2*j+1]);
        hf[2*j]   = __half2float(__low2half(h));
        hf[2*j+1] = __half2float(__high2half(h));
        lf[2*j]   = x[2*j]   - hf[2*j];
        lf[2*j+1] = x[2*j+1] - hf[2*j+1];
        hh[j] = h2u(h);
    }
    *(uint4*)(g_khi + i) = make_uint4(hh[0], hh[1], hh[2], hh[3]);
    *(uint2*)(g_klo8 + i) = make_uint2(
        pk8(lf[0]*SCL, lf[1]*SCL, lf[2]*SCL, lf[3]*SCL),
        pk8(lf[4]*SCL, lf[5]*SCL, lf[6]*SCL, lf[7]*SCL));
    *(uint2*)(g_khi8 + i) = make_uint2(
        pk8(hf[0], hf[1], hf[2], hf[3]),
        pk8(hf[4], hf[5], hf[6], hf[7]));
}

// ---------------- Main attention kernel ----------------
__global__ __launch_bounds__(NT, 2)
void attn_hmma(const float* __restrict__ out_state,
               float* __restrict__ out)
{
    extern __shared__ __align__(16) char smb[];
    const uint32_t s_base = smem_u32(smb);

    const int t    = threadIdx.x;
    const int wm   = t >> 5;
    const int lane = t & 31;
    const int g    = lane >> 2;
    const int tc   = lane & 3;
    const int q0   = blockIdx.x * BM;
    const int b    = blockIdx.y;

    const float*   q_g   = out_state + (size_t)b * Qlen * Hdim;
    const __half*  khiB  = g_khi  + (size_t)b * Klen * Hdim;
    const uint8_t* klo8B = g_klo8 + (size_t)b * Klen * Hdim;
    const uint8_t* khi8B = g_khi8 + (size_t)b * Klen * Hdim;
    float*         o_g   = out + (size_t)b * Qlen * Hdim;

    // ---- Q fragments ----
    uint32_t qhi[8][4];      // fp16 hi A-frags (pass 1), k16 steps
    uint32_t q8a[4][4];      // e4m3(qhi) A-frags, k32 steps  (term Qhi*Klo)
    uint32_t q8b[4][4];      // e4m3((q-qhi)*2^12) A-frags    (term Qlo*Khi)
    {
        const float* qb = q_g + (size_t)(q0 + wm * 16 + g) * Hdim;

        // fp16 frags: h = kk*16 + tc*2 (+8), rows g, g+8
        #pragma unroll
        for (int kk = 0; kk < 8; ++kk) {
            const int h0 = kk * 16 + tc * 2;
            float2 x00 = *(const float2*)(qb + h0);
            float2 x10 = *(const float2*)(qb + 8 * Hdim + h0);
            float2 x01 = *(const float2*)(qb + h0 + 8);
            float2 x11 = *(const float2*)(qb + 8 * Hdim + h0 + 8);
            x00.x = tanhf(x00.x) * LOG2E; x00.y = tanhf(x00.y) * LOG2E;
            x10.x = tanhf(x10.x) * LOG2E; x10.y = tanhf(x10.y) * LOG2E;
            x01.x = tanhf(x01.x) * LOG2E; x01.y = tanhf(x01.y) * LOG2E;
            x11.x = tanhf(x11.x) * LOG2E; x11.y = tanhf(x11.y) * LOG2E;
            uint32_t dum;
            split_h2(x00.x, x00.y, qhi[kk][0], dum);
            split_h2(x10.x, x10.y, qhi[kk][1], dum);
            split_h2(x01.x, x01.y, qhi[kk][2], dum);
            split_h2(x11.x, x11.y, qhi[kk][3], dum);
        }

        // fp8 frags: h = kq*32 + tc*4 (+16), rows g, g+8 (a0=rowg k0, a1=rowg+8 k0, a2=rowg k16, a3=rowg+8 k16)
        #pragma unroll
        for (int kq = 0; kq < 4; ++kq) {
            const int h0 = kq * 32 + tc * 4;
            float4 va = *(const float4*)(qb + h0);
            float4 vc = *(const float4*)(qb + 8 * Hdim + h0);
            float4 vb = *(const float4*)(qb + h0 + 16);
            float4 vd = *(const float4*)(qb + 8 * Hdim + h0 + 16);
            float e[4][4] = {{va.x,va.y,va.z,va.w},{vc.x,vc.y,vc.z,vc.w},
                             {vb.x,vb.y,vb.z,vb.w},{vd.x,vd.y,vd.z,vd.w}};
            #pragma unroll
            for (int r = 0; r < 4; ++r) {
                float hf[4], lf[4];
                #pragma unroll
                for (int c = 0; c < 4; ++c) {
                    float tq = tanhf(e[r][c]) * LOG2E;
                    hf[c] = __half2float(__float2half_rn(tq));
                    lf[c] = (tq - hf[c]) * SCL;
                }
                q8a[kq][r] = pk8(hf[0], hf[1], hf[2], hf[3]);
                q8b[kq][r] = pk8(lf[0], lf[1], lf[2], lf[3]);
            }
        }
    }

    // O accumulator + l-column
    float o[16][4];
    #pragma unroll
    for (int n = 0; n < 16; ++n)
        #pragma unroll
        for (int j = 0; j < 4; ++j) o[n][j] = 0.f;
    float ol[4] = {0.f, 0.f, 0.f, 0.f};

    float m0 = -INFINITY, m1 = -INFINITY;

    // ---- tile loader: hi16 (swz2) + lo8/hi8 (swz8) ----
    auto load_tile = [&](int kt, uint32_t sb) {
        const __half*  srcH = khiB  + (size_t)kt * BN * Hdim;
        const uint8_t* srcL = klo8B + (size_t)kt * BN * Hdim;
        const uint8_t* srcG = khi8B + (size_t)kt * BN * Hdim;
        #pragma unroll
        for (int j = 0; j < 8; ++j) {
            const int idx = j * NT + t;        // 0..1023
            const int row = idx >> 4;
            const int ch  = idx & 15;
            cpa16(sb + swz2(row, ch << 4), srcH + (size_t)row * Hdim + ch * 8);
        }
        #pragma unroll
        for (int j = 0; j < 4; ++j) {
            const int idx = j * NT + t;        // 0..511
            const int row = idx >> 3;
            const int ch  = idx & 7;
            const uint32_t d = swz8(row, ch << 4);
            cpa16(sb + OFF_LO8 + d, srcL + (size_t)row * Hdim + ch * 16);
            cpa16(sb + OFF_HI8 + d, srcG + (size_t)row * Hdim + ch * 16);
        }
        CP_COMMIT();
    };

    load_tile(0, s_base);

    for (int kt = 0; kt < NTILE; ++kt) {
        CP_WAIT0();
        __syncthreads();

        if (kt + 1 < NTILE)
            load_tile(kt + 1, s_base + ((kt + 1) & 1) * TILE_BYTES);

        const uint32_t s_hi  = s_base + (kt & 1) * TILE_BYTES;
        const uint32_t s_lo8 = s_hi + OFF_LO8;
        const uint32_t s_hi8 = s_hi + OFF_HI8;

        // ---- QK^T cross terms (fp8, k32): s2 = Qhi8*Klo8' + Qlo8'*Khi8 ----
        float s2[8][4];
        #pragma unroll
        for (int n = 0; n < 8; ++n)
            #pragma unroll
            for (int j = 0; j < 4; ++j) s2[n][j] = 0.f;

        #pragma unroll
        for (int kq = 0; kq < 4; ++kq) {
            uint32_t fl[4][4], fh[4][4];
            #pragma unroll
            for (int np = 0; np < 4; ++np) {
                const int row  = np * 16 + (lane & 7) + ((lane >> 4) << 3);
                const int colb = kq * 32 + ((lane >> 3) & 1) * 16;   // bytes (fp8)
                const uint32_t a = swz8(row, colb);
                ldsm_x4(fl[np][0], fl[np][1], fl[np][2], fl[np][3], s_lo8 + a);
                ldsm_x4(fh[np][0], fh[np][1], fh[np][2], fh[np][3], s_hi8 + a);
            }
            #pragma unroll
            for (int n = 0; n < 8; ++n)
                mma_fp8(s2[n], q8a[kq], fl[n >> 1][(n & 1) * 2], fl[n >> 1][(n & 1) * 2 + 1]);
            #pragma unroll
            for (int n = 0; n < 8; ++n)
                mma_fp8(s2[n], q8b[kq], fh[n >> 1][(n & 1) * 2], fh[n >> 1][(n & 1) * 2 + 1]);
        }

        // ---- QK^T main pass (fp16): s = Qhi . Khi ----
        float s[8][4];
        #pragma unroll
        for (int n = 0; n < 8; ++n)
            #pragma unroll
            for (int j = 0; j < 4; ++j) s[n][j] = 0.f;

        #pragma unroll
        for (int kk = 0; kk < 8; ++kk) {
            uint32_t bh[4][4];
            #pragma unroll
            for (int np = 0; np < 4; ++np) {
                const int row = np * 16 + (lane & 7) + ((lane >> 4) << 3);
                const int col = kk * 32 + ((lane >> 3) & 1) * 16;   // bytes (fp16)
                ldsm_x4(bh[np][0], bh[np][1], bh[np][2], bh[np][3], s_hi + swz2(row, col));
            }
            #pragma unroll
            for (int n = 0; n < 8; ++n)
                mma16816(s[n], qhi[kk], bh[n >> 1][(n & 1) * 2], bh[n >> 1][(n & 1) * 2 + 1]);
        }

        // fold cross terms (scale 2^-12)
        #pragma unroll
        for (int n = 0; n < 8; ++n)
            #pragma unroll
            for (int j = 0; j < 4; ++j) s[n][j] = fmaf(s2[n][j], INVSCL, s[n][j]);

        // ---- Online max (warp-local); l via ones-MMA ----
        float t0 = -INFINITY, t1 = -INFINITY;
        #pragma unroll
        for (int n = 0; n < 8; ++n) {
            t0 = fmaxf(t0, fmaxf(s[n][0], s[n][1]));
            t1 = fmaxf(t1, fmaxf(s[n][2], s[n][3]));
        }
        t0 = fmaxf(t0, __shfl_xor_sync(0xffffffffu, t0, 1));
        t0 = fmaxf(t0, __shfl_xor_sync(0xffffffffu, t0, 2));
        t1 = fmaxf(t1, __shfl_xor_sync(0xffffffffu, t1, 1));
        t1 = fmaxf(t1, __shfl_xor_sync(0xffffffffu, t1, 2));

        const float mn0 = fmaxf(m0, t0), mn1 = fmaxf(m1, t1);
        const bool updated = (mn0 != m0) | (mn1 != m1);
        const bool any_up  = __any_sync(0xffffffffu, updated);
        const float al0 = ex2f(m0 - mn0), al1 = ex2f(m1 - mn1);
        m0 = mn0; m1 = mn1;

        // ---- p = 2^(s-m) via packed fp16 ex2 -> pa fragments ----
        uint32_t pa[4][4];
        #pragma unroll
        for (int n = 0; n < 8; ++n) {
            uint32_t ua = h2u(__floats2half2_rn(s[n][0] - mn0, s[n][1] - mn0));
            uint32_t ub = h2u(__floats2half2_rn(s[n][2] - mn1, s[n][3] - mn1));
            pa[n >> 1][(n & 1) * 2]     = ex2h2(ua);
            pa[n >> 1][(n & 1) * 2 + 1] = ex2h2(ub);
        }

        if (any_up) {
            #pragma unroll
            for (int n = 0; n < 16; ++n) {
                o[n][0] *= al0; o[n][1] *= al0;
                o[n][2] *= al1; o[n][3] *= al1;
            }
            ol[0] *= al0; ol[1] *= al0; ol[2] *= al1; ol[3] *= al1;
        }

        // ---- PV: O += P * V; l via constant all-ones B fragment ----
        #pragma unroll
        for (int kg = 0; kg < 4; ++kg) {
            #pragma unroll
            for (int hp = 0; hp < 8; ++hp) {
                const int row = kg * 16 + (lane & 7) + (((lane >> 3) & 1) << 3);
                const int col = hp * 32 + ((lane >> 4) & 1) * 16;
                uint32_t r0, r1, r2, r3;
                ldsm_x4_t(r0, r1, r2, r3, s_hi + swz2(row, col));
                mma16816(o[2*hp],     pa[kg], r0, r1);
                mma16816(o[2*hp + 1], pa[kg], r2, r3);
            }
            mma16816(ol, pa[kg], ONESF16X2, ONESF16X2);
        }
    }

    // ---- Epilogue: normalize and store ----
    const float inv0 = 1.0f / ol[0];
    const float inv1 = 1.0f / ol[2];
    float* ob = o_g + (size_t)(q0 + wm * 16 + g) * Hdim;
    #pragma unroll
    for (int n = 0; n < 16; ++n) {
        const int h = n * 8 + tc * 2;
        *(float2*)(ob + h)            = make_float2(o[n][0] * inv0, o[n][1] * inv0);
        *(float2*)(ob + 8 * Hdim + h) = make_float2(o[n][2] * inv1, o[n][3] * inv1);
    }
}

extern "C" void kernel_launch(void* const* d_in, const int* in_sizes, int n_in,
                              void* d_out, int out_size)
{
    const float* out_state = (const float*)d_in[0];
    const float* history   = (const float*)d_in[1];
    float*       out       = (float*)d_out;

    // 1) split history fp32 -> fp16 hi + fp8 cross operands
    prep_split<<<KTOT / 8 / 256, 256>>>(history);

    // 2) fused flash attention: fp16 main pass + ldsm-fed fp8 cross pass
    cudaFuncSetAttribute(attn_hmma, cudaFuncAttributeMaxDynamicSharedMemorySize, SMEM_BYTES);
    dim3 grid(Qlen / BM, Bsz);
    attn_hmma<<<grid, NT, SMEM_BYTES>>>(out_state, out);
}

// round 11
// speedup vs baseline: 1.2185x; 1.2185x over previous
#include <cuda_runtime.h>
#include <cuda_fp16.h>
#include <stdint.h>
#include <math.h>

// Problem constants (fixed by dataset)
#define Bsz  8
#define Qlen 2048
#define Klen 2048
#define Hdim 128
#define BM   64          // queries per CTA
#define BN   64          // keys per tile
#define NT   128         // 4 warps
#define NTILE (Klen / BN)

#define KTOT (Bsz * Klen * Hdim)   // 2,097,152 elements

// Pre-split history scratch (fp16 hi + residual lo), row-major [b][key][h]
__device__ __align__(16) __half g_khi[KTOT];
__device__ __align__(16) __half g_klo[KTOT];

// stage: [hi fp16 swizzled 16KB][lo fp16 swizzled 16KB]; 3 stages + pa stash
#define TILE_HI_BYTES 16384
#define TILE_BYTES    32768
#define STASH_OFF     (3 * TILE_BYTES)
#define STASH_BYTES   8192                     // 4 warps x 32 lanes x 64B
#define SMEM_BYTES    (STASH_OFF + STASH_BYTES)

#define LOG2E 1.4426950408889634f
#define ONESF16X2 0x3C003C00u     // half2(1.0, 1.0)

__device__ __forceinline__ uint32_t smem_u32(const void* p) {
    uint32_t a;
    asm("{ .reg .u64 t; cvta.to.shared.u64 t, %1; cvt.u32.u64 %0, t; }" : "=r"(a) : "l"(p));
    return a;
}
__device__ __forceinline__ uint32_t h2u(__half2 h) { return *reinterpret_cast<uint32_t*>(&h); }
__device__ __forceinline__ float ex2f(float x) {
    float y; asm("ex2.approx.ftz.f32 %0, %1;" : "=f"(y) : "f"(x)); return y;
}
__device__ __forceinline__ uint32_t ex2h2(uint32_t x) {
    uint32_t y; asm("ex2.approx.f16x2 %0, %1;" : "=r"(y) : "r"(x)); return y;
}

// fp32 pair -> fp16 hi + fp16 residual(lo), packed half2
__device__ __forceinline__ void split_h2(float x, float y, uint32_t& hi, uint32_t& lo) {
    __half2 h = __floats2half2_rn(x, y);
    float rx = x - __half2float(__low2half(h));
    float ry = y - __half2float(__high2half(h));
    __half2 l = __floats2half2_rn(rx, ry);
    hi = h2u(h); lo = h2u(l);
}

// XOR-swizzled tile offset: row in [0,64), bytecol in [0,256)
__device__ __forceinline__ uint32_t swz2(int row, int bytecol) {
    int ch = bytecol >> 4;
    int chs = (ch & 8) | ((ch ^ row) & 7);
    return (uint32_t)(row * 256 + (chs << 4));
}

__device__ __forceinline__ void cpa16(uint32_t dst, const void* src) {
    asm volatile("cp.async.cg.shared.global [%0], [%1], 16;" :: "r"(dst), "l"(src));
}
#define CP_COMMIT() asm volatile("cp.async.commit_group;" ::: "memory")
#define CP_WAIT1()  asm volatile("cp.async.wait_group 1;" ::: "memory")

__device__ __forceinline__ void ldsm_x4(uint32_t& r0, uint32_t& r1, uint32_t& r2, uint32_t& r3,
                                        uint32_t addr) {
    asm volatile("ldmatrix.sync.aligned.m8n8.x4.shared.b16 {%0,%1,%2,%3}, [%4];"
                 : "=r"(r0), "=r"(r1), "=r"(r2), "=r"(r3) : "r"(addr));
}
__device__ __forceinline__ void ldsm_x4_t(uint32_t& r0, uint32_t& r1, uint32_t& r2, uint32_t& r3,
                                          uint32_t addr) {
    asm volatile("ldmatrix.sync.aligned.m8n8.x4.trans.shared.b16 {%0,%1,%2,%3}, [%4];"
                 : "=r"(r0), "=r"(r1), "=r"(r2), "=r"(r3) : "r"(addr));
}
// D(16x8,f32) += A(16x16,f16) * B(16x8,f16)
__device__ __forceinline__ void mma16816(float* d, const uint32_t* a, uint32_t b0, uint32_t b1) {
    asm volatile("mma.sync.aligned.m16n8k16.row.col.f32.f16.f16.f32 "
                 "{%0,%1,%2,%3}, {%4,%5,%6,%7}, {%8,%9}, {%0,%1,%2,%3};"
                 : "+f"(d[0]), "+f"(d[1]), "+f"(d[2]), "+f"(d[3])
                 : "r"(a[0]), "r"(a[1]), "r"(a[2]), "r"(a[3]), "r"(b0), "r"(b1));
}

// ---------------- Pre-pass: split history fp32 -> fp16 hi/lo ----------------
__global__ __launch_bounds__(256)
void prep_split(const float* __restrict__ history)
{
    const size_t i = ((size_t)blockIdx.x * 256 + threadIdx.x) * 8;
    float4 a = *(const float4*)(history + i);
    float4 b = *(const float4*)(history + i + 4);
    uint32_t h[4], l[4];
    split_h2(a.x, a.y, h[0], l[0]);
    split_h2(a.z, a.w, h[1], l[1]);
    split_h2(b.x, b.y, h[2], l[2]);
    split_h2(b.z, b.w, h[3], l[3]);
    *(uint4*)(g_khi + i) = make_uint4(h[0], h[1], h[2], h[3]);
    *(uint4*)(g_klo + i) = make_uint4(l[0], l[1], l[2], l[3]);
}

// ---------------- Main attention kernel ----------------
__global__ __launch_bounds__(NT, 2)
void attn_hmma(const float* __restrict__ out_state,
               float* __restrict__ out)
{
    extern __shared__ __align__(16) char smb[];
    const uint32_t s_base = smem_u32(smb);

    const int t    = threadIdx.x;
    const int wm   = t >> 5;          // warp id = query-row group
    const int lane = t & 31;
    const int g    = lane >> 2;       // row within fragment group (0..7)
    const int tc   = lane & 3;        // col pair within group
    const int q0   = blockIdx.x * BM;
    const int b    = blockIdx.y;

    const float*  q_g  = out_state + (size_t)b * Qlen * Hdim;
    const __half* khiB = g_khi + (size_t)b * Klen * Hdim;
    const __half* kloB = g_klo + (size_t)b * Klen * Hdim;
    float*        o_g  = out + (size_t)b * Qlen * Hdim;

    // per-warp pa stash (smem): 4 chunks x 512B, lane-contiguous -> conflict-free
    char* stash = smb + STASH_OFF + wm * 2048;

    // ---- Q A-fragments: tanh * log2e, split fp16 hi/lo ----
    uint32_t qhi[8][4], qlo[8][4];
    {
        const float* qb = q_g + (size_t)(q0 + wm * 16 + g) * Hdim;
        #pragma unroll
        for (int kk = 0; kk < 8; ++kk) {
            const int h0 = kk * 16 + tc * 2;
            float2 x00 = *(const float2*)(qb + h0);
            float2 x10 = *(const float2*)(qb + 8 * Hdim + h0);
            float2 x01 = *(const float2*)(qb + h0 + 8);
            float2 x11 = *(const float2*)(qb + 8 * Hdim + h0 + 8);
            x00.x = tanhf(x00.x) * LOG2E; x00.y = tanhf(x00.y) * LOG2E;
            x10.x = tanhf(x10.x) * LOG2E; x10.y = tanhf(x10.y) * LOG2E;
            x01.x = tanhf(x01.x) * LOG2E; x01.y = tanhf(x01.y) * LOG2E;
            x11.x = tanhf(x11.x) * LOG2E; x11.y = tanhf(x11.y) * LOG2E;
            split_h2(x00.x, x00.y, qhi[kk][0], qlo[kk][0]);
            split_h2(x10.x, x10.y, qhi[kk][1], qlo[kk][1]);
            split_h2(x01.x, x01.y, qhi[kk][2], qlo[kk][2]);
            split_h2(x11.x, x11.y, qhi[kk][3], qlo[kk][3]);
        }
    }

    // O accumulator + l-column (ones-MMA)
    float o[16][4];
    #pragma unroll
    for (int n = 0; n < 16; ++n)
        #pragma unroll
        for (int j = 0; j < 4; ++j) o[n][j] = 0.f;
    float ol[4] = {0.f, 0.f, 0.f, 0.f};

    float m0 = -INFINITY, m1 = -INFINITY;
    float alp0 = 1.f, alp1 = 1.f;     // alphas from previous tile's softmax
    bool  prev_up = false;

    // ---- tile loader ----
    auto load_tile = [&](int kt, int buf) {
        const uint32_t sb = s_base + (uint32_t)buf * TILE_BYTES;
        const __half* srcH = khiB + (size_t)kt * BN * Hdim;
        const __half* srcL = kloB + (size_t)kt * BN * Hdim;
        #pragma unroll
        for (int j = 0; j < 8; ++j) {
            const int idx = j * NT + t;        // 0..1023
            const int row = idx >> 4;
            const int ch  = idx & 15;
            const uint32_t d = sb + swz2(row, ch << 4);
            cpa16(d,                 srcH + (size_t)row * Hdim + ch * 8);
            cpa16(d + TILE_HI_BYTES, srcL + (size_t)row * Hdim + ch * 8);
        }
    };

    // rescale + deferred PV over a given buffer (pa from stash)
    auto pv_prev = [&](int buf) {
        if (prev_up) {
            #pragma unroll
            for (int n = 0; n < 16; ++n) {
                o[n][0] *= alp0; o[n][1] *= alp0;
                o[n][2] *= alp1; o[n][3] *= alp1;
            }
            ol[0] *= alp0; ol[1] *= alp0; ol[2] *= alp1; ol[3] *= alp1;
        }
        const uint32_t s_hi = s_base + (uint32_t)buf * TILE_BYTES;
        #pragma unroll
        for (int kg = 0; kg < 4; ++kg) {
            uint4 pv = *(const uint4*)(stash + kg * 512 + lane * 16);
            uint32_t pap[4] = {pv.x, pv.y, pv.z, pv.w};
            #pragma unroll
            for (int hp = 0; hp < 8; ++hp) {
                const int row = kg * 16 + (lane & 7) + (((lane >> 3) & 1) << 3);
                const int col = hp * 32 + ((lane >> 4) & 1) * 16;
                uint32_t r0, r1, r2, r3;
                ldsm_x4_t(r0, r1, r2, r3, s_hi + swz2(row, col));
                mma16816(o[2*hp],     pap, r0, r1);
                mma16816(o[2*hp + 1], pap, r2, r3);
            }
            mma16816(ol, pap, ONESF16X2, ONESF16X2);
        }
    };

    // ---- prologue: prefetch tiles 0,1 into buffers 0,1 ----
    load_tile(0, 0); CP_COMMIT();
    load_tile(1, 1); CP_COMMIT();

    for (int kt = 0; kt < NTILE; ++kt) {
        CP_WAIT1();          // tile kt landed (all but newest group done)
        __syncthreads();     // visible to all warps

        const int bufc = kt % 3;
        const uint32_t s_hi = s_base + (uint32_t)bufc * TILE_BYTES;
        const uint32_t s_lo = s_hi + TILE_HI_BYTES;

        // ---- QK^T: S (16x64 per warp), 3-pass split (base-2 domain) ----
        float s[8][4];
        #pragma unroll
        for (int n = 0; n < 8; ++n)
            #pragma unroll
            for (int j = 0; j < 4; ++j) s[n][j] = 0.f;

        #pragma unroll
        for (int kk = 0; kk < 8; ++kk) {
            uint32_t bh[4][4], bl[4][4];
            #pragma unroll
            for (int np = 0; np < 4; ++np) {
                const int row = np * 16 + (lane & 7) + ((lane >> 4) << 3);
                const int col = kk * 32 + ((lane >> 3) & 1) * 16;   // bytes
                const uint32_t a = swz2(row, col);
                ldsm_x4(bh[np][0], bh[np][1], bh[np][2], bh[np][3], s_hi + a);
                ldsm_x4(bl[np][0], bl[np][1], bl[np][2], bl[np][3], s_lo + a);
            }
            #pragma unroll
            for (int n = 0; n < 8; ++n)
                mma16816(s[n], qhi[kk], bh[n >> 1][(n & 1) * 2], bh[n >> 1][(n & 1) * 2 + 1]);
            #pragma unroll
            for (int n = 0; n < 8; ++n)
                mma16816(s[n], qhi[kk], bl[n >> 1][(n & 1) * 2], bl[n >> 1][(n & 1) * 2 + 1]);
            #pragma unroll
            for (int n = 0; n < 8; ++n)
                mma16816(s[n], qlo[kk], bh[n >> 1][(n & 1) * 2], bh[n >> 1][(n & 1) * 2 + 1]);
        }

        // ---- deferred PV of tile kt-1 (independent of s -> fills softmax stalls) ----
        if (kt > 0) pv_prev((kt - 1) % 3);

        // ---- softmax(kt): max-reduce, alphas for NEXT iter, pa -> stash ----
        float t0 = -INFINITY, t1 = -INFINITY;
        #pragma unroll
        for (int n = 0; n < 8; ++n) {
            t0 = fmaxf(t0, fmaxf(s[n][0], s[n][1]));
            t1 = fmaxf(t1, fmaxf(s[n][2], s[n][3]));
        }
        t0 = fmaxf(t0, __shfl_xor_sync(0xffffffffu, t0, 1));
        t0 = fmaxf(t0, __shfl_xor_sync(0xffffffffu, t0, 2));
        t1 = fmaxf(t1, __shfl_xor_sync(0xffffffffu, t1, 1));
        t1 = fmaxf(t1, __shfl_xor_sync(0xffffffffu, t1, 2));

        const float mn0 = fmaxf(m0, t0), mn1 = fmaxf(m1, t1);
        const bool updated = (mn0 != m0) | (mn1 != m1);
        prev_up = __any_sync(0xffffffffu, updated);
        alp0 = ex2f(m0 - mn0); alp1 = ex2f(m1 - mn1);
        m0 = mn0; m1 = mn1;

        #pragma unroll
        for (int n = 0; n < 8; n += 2) {
            uint32_t pr[4];
            pr[0] = ex2h2(h2u(__floats2half2_rn(s[n][0]   - mn0, s[n][1]   - mn0)));
            pr[1] = ex2h2(h2u(__floats2half2_rn(s[n][2]   - mn1, s[n][3]   - mn1)));
            pr[2] = ex2h2(h2u(__floats2half2_rn(s[n+1][0] - mn0, s[n+1][1] - mn0)));
            pr[3] = ex2h2(h2u(__floats2half2_rn(s[n+1][2] - mn1, s[n+1][3] - mn1)));
            *(uint4*)(stash + (n >> 1) * 512 + lane * 16) =
                make_uint4(pr[0], pr[1], pr[2], pr[3]);
        }

        __syncthreads();     // all warps done reading buf (kt-1)%3 before reuse

        if (kt + 2 < NTILE) load_tile(kt + 2, (kt + 2) % 3);
        CP_COMMIT();         // commit (possibly empty) to keep group accounting
    }

    // ---- final deferred PV of last tile ----
    pv_prev((NTILE - 1) % 3);

    // ---- Epilogue: normalize by l and store ----
    const float inv0 = 1.0f / ol[0];
    const float inv1 = 1.0f / ol[2];
    float* ob = o_g + (size_t)(q0 + wm * 16 + g) * Hdim;
    #pragma unroll
    for (int n = 0; n < 16; ++n) {
        const int h = n * 8 + tc * 2;
        *(float2*)(ob + h)            = make_float2(o[n][0] * inv0, o[n][1] * inv0);
        *(float2*)(ob + 8 * Hdim + h) = make_float2(o[n][2] * inv1, o[n][3] * inv1);
    }
}

extern "C" void kernel_launch(void* const* d_in, const int* in_sizes, int n_in,
                              void* d_out, int out_size)
{
    const float* out_state = (const float*)d_in[0];
    const float* history   = (const float*)d_in[1];
    float*       out       = (float*)d_out;

    // 1) split history fp32 -> fp16 hi/lo scratch
    prep_split<<<KTOT / 8 / 256, 256>>>(history);

    // 2) fused flash attention on HMMA, tile-skewed PV pipeline
    cudaFuncSetAttribute(attn_hmma, cudaFuncAttributeMaxDynamicSharedMemorySize, SMEM_BYTES);
    dim3 grid(Qlen / BM, Bsz);
    attn_hmma<<<grid, NT, SMEM_BYTES>>>(out_state, out);
}